// round 7
// baseline (speedup 1.0000x reference)
#include <cuda_runtime.h>
#include <cstdint>

#define NN 50000
#define NE 800000
#define F  128
#define SCAN_B 256
#define NBLK ((NN + SCAN_B - 1) / SCAN_B)   // 196

#define BM   128          // gemm rows per block
#define SW   132          // Hs padded row stride (floats)
#define WPAD 17           // Wpk padded nt stride (float4s)

// ---------------- device scratch (no allocations allowed) -------------------
__device__ int   g_deg_out_i[NN];
__device__ int   g_deg_in_i[NN];
__device__ int   g_row_start[NN];
__device__ int   g_cursor[NN];
__device__ float g_scale_out[NN];
__device__ int   g_perm_src[NE];
__device__ float g_h[NN * F];
__device__ float4 g_Wpk[16 * 32 * 16];      // fragment-ordered W (hi0,hi1,lo0,lo1)
__device__ int   g_scan_status[NBLK];       // 0=none, 1=aggregate, 2=prefix
__device__ int   g_scan_agg[NBLK];
__device__ int   g_scan_pref[NBLK];

__device__ __forceinline__ float to_tf32(float v) {
    uint32_t b;
    asm("cvt.rna.tf32.f32 %0, %1;" : "=r"(b) : "f"(v));
    return __uint_as_float(b);
}

// ---------------------------------------------------------------------------
// 1) init: zero degrees + scan statuses, and build fragment-ordered W split
// ---------------------------------------------------------------------------
__global__ void init_kernel(const float* __restrict__ weight) {
    int i = blockIdx.x * blockDim.x + threadIdx.x;
    if (i < NN) { g_deg_out_i[i] = 0; g_deg_in_i[i] = 0; }
    if (i < NBLK) g_scan_status[i] = 0;
    if (i < 16 * 32 * 16) {
        int nt   = i & 15;
        int rest = i >> 4;
        int lane = rest & 31;
        int ks   = rest >> 5;
        int tg   = lane & 3;
        int gid  = lane >> 2;
        int k0 = ks * 8, n0 = nt * 8;
        float w0 = weight[(k0 + tg) * F + n0 + gid];
        float w1 = weight[(k0 + tg + 4) * F + n0 + gid];
        float h0 = to_tf32(w0), h1 = to_tf32(w1);
        g_Wpk[i] = make_float4(h0, h1, to_tf32(w0 - h0), to_tf32(w1 - h1));
    }
}

// ---------------------------------------------------------------------------
// 2) degree histograms
// ---------------------------------------------------------------------------
__global__ void deg_kernel(const int* __restrict__ src, const int* __restrict__ dst) {
    int e = blockIdx.x * blockDim.x + threadIdx.x;
    if (e < NE) {
        atomicAdd(&g_deg_out_i[src[e]], 1);
        atomicAdd(&g_deg_in_i[dst[e]], 1);
    }
}

// ---------------------------------------------------------------------------
// 3) single-pass exclusive scan (decoupled lookback) + cursor + scale_out
// ---------------------------------------------------------------------------
__global__ void __launch_bounds__(SCAN_B)
scan_kernel() {
    int bid  = blockIdx.x;
    int idx  = bid * SCAN_B + threadIdx.x;
    int lane = threadIdx.x & 31;
    int w    = threadIdx.x >> 5;
    int v    = (idx < NN) ? g_deg_in_i[idx] : 0;

    int x = v;
#pragma unroll
    for (int o = 1; o < 32; o <<= 1) {
        int t = __shfl_up_sync(0xffffffffu, x, o);
        if (lane >= o) x += t;
    }
    __shared__ int wsum[8];
    __shared__ int s_base;
    if (lane == 31) wsum[w] = x;
    __syncthreads();
    if (threadIdx.x < 8) {
        int s = wsum[threadIdx.x];
#pragma unroll
        for (int o = 1; o < 8; o <<= 1) {
            int t = __shfl_up_sync(0xffu, s, o);
            if ((int)threadIdx.x >= o) s += t;
        }
        wsum[threadIdx.x] = s;
    }
    __syncthreads();
    int woff  = (w > 0) ? wsum[w - 1] : 0;
    int excl  = woff + x - v;        // exclusive within block
    int total = wsum[7];

    if (threadIdx.x == 0) {
        if (bid == 0) {
            g_scan_pref[0] = total;
            __threadfence();
            atomicExch(&g_scan_status[0], 2);
            s_base = 0;
        } else {
            g_scan_agg[bid] = total;
            __threadfence();
            atomicExch(&g_scan_status[bid], 1);
            int run = 0;
            for (int j = bid - 1; j >= 0; j--) {
                int s;
                do { s = atomicAdd(&g_scan_status[j], 0); } while (s == 0);
                __threadfence();
                if (s == 2) { run += g_scan_pref[j]; break; }
                run += g_scan_agg[j];
            }
            g_scan_pref[bid] = run + total;
            __threadfence();
            atomicExch(&g_scan_status[bid], 2);
            s_base = run;
        }
    }
    __syncthreads();
    if (idx < NN) {
        int rs = s_base + excl;
        g_row_start[idx] = rs;
        g_cursor[idx]    = rs;
        g_scale_out[idx] = rsqrtf(fmaxf((float)g_deg_out_i[idx], 1.0f));
    }
}

// ---------------------------------------------------------------------------
// 4) counting-sort scatter: 4 edges per thread (NE % 4 == 0)
// ---------------------------------------------------------------------------
__global__ void scatter_kernel(const int* __restrict__ src, const int* __restrict__ dst) {
    int t = blockIdx.x * blockDim.x + threadIdx.x;
    int e0 = t * 4;
    if (e0 < NE) {
        int4 d = *reinterpret_cast<const int4*>(dst + e0);
        int4 s = *reinterpret_cast<const int4*>(src + e0);
        int p0 = atomicAdd(&g_cursor[d.x], 1);
        int p1 = atomicAdd(&g_cursor[d.y], 1);
        int p2 = atomicAdd(&g_cursor[d.z], 1);
        int p3 = atomicAdd(&g_cursor[d.w], 1);
        g_perm_src[p0] = s.x;
        g_perm_src[p1] = s.y;
        g_perm_src[p2] = s.z;
        g_perm_src[p3] = s.w;
    }
}

// ---------------------------------------------------------------------------
// 5) CSR aggregation: one warp per node, both norms folded in.
// ---------------------------------------------------------------------------
__global__ void __launch_bounds__(256)
agg_kernel(const float* __restrict__ x) {
    int gtid = blockIdx.x * blockDim.x + threadIdx.x;
    int node = gtid >> 5;
    int lane = threadIdx.x & 31;
    if (node >= NN) return;

    int start = g_row_start[node];
    int len   = g_deg_in_i[node];
    const int* ps = g_perm_src + start;
    const float4* x4 = reinterpret_cast<const float4*>(x);

    float4 acc = make_float4(0.f, 0.f, 0.f, 0.f);
    int i = 0;
    for (; i + 4 <= len; i += 4) {
        int s0 = ps[i], s1 = ps[i + 1], s2 = ps[i + 2], s3 = ps[i + 3];
        float c0 = g_scale_out[s0], c1 = g_scale_out[s1];
        float c2 = g_scale_out[s2], c3 = g_scale_out[s3];
        float4 a0 = x4[(size_t)s0 * 32 + lane];
        float4 a1 = x4[(size_t)s1 * 32 + lane];
        float4 a2 = x4[(size_t)s2 * 32 + lane];
        float4 a3 = x4[(size_t)s3 * 32 + lane];
        acc.x += c0 * a0.x; acc.y += c0 * a0.y; acc.z += c0 * a0.z; acc.w += c0 * a0.w;
        acc.x += c1 * a1.x; acc.y += c1 * a1.y; acc.z += c1 * a1.z; acc.w += c1 * a1.w;
        acc.x += c2 * a2.x; acc.y += c2 * a2.y; acc.z += c2 * a2.z; acc.w += c2 * a2.w;
        acc.x += c3 * a3.x; acc.y += c3 * a3.y; acc.z += c3 * a3.z; acc.w += c3 * a3.w;
    }
    for (; i < len; i++) {
        int s0 = ps[i];
        float c0 = g_scale_out[s0];
        float4 a0 = x4[(size_t)s0 * 32 + lane];
        acc.x += c0 * a0.x; acc.y += c0 * a0.y; acc.z += c0 * a0.z; acc.w += c0 * a0.w;
    }
    float inv = rsqrtf(fmaxf((float)len, 1.0f));
    acc.x *= inv; acc.y *= inv; acc.z *= inv; acc.w *= inv;
    reinterpret_cast<float4*>(g_h + (size_t)node * F)[lane] = acc;
}

// ---------------------------------------------------------------------------
// 6) Tensor-core GEMM (3xTF32) with packed B fragments: out = h @ W + bias
//    smem: Wpk[16][32][17] float4 (139264B) + Hs[128][132] (67584B) + bias
//    Inner loop: ONE LDS.128 per (ks,nt) for all 4 B fragment words.
// ---------------------------------------------------------------------------
__device__ __forceinline__ void mma_tf32(float& d0, float& d1, float& d2, float& d3,
                                         uint32_t a0, uint32_t a1, uint32_t a2, uint32_t a3,
                                         uint32_t b0, uint32_t b1) {
    asm volatile(
        "mma.sync.aligned.m16n8k8.row.col.f32.tf32.tf32.f32 "
        "{%0,%1,%2,%3}, {%4,%5,%6,%7}, {%8,%9}, {%0,%1,%2,%3};"
        : "+f"(d0), "+f"(d1), "+f"(d2), "+f"(d3)
        : "r"(a0), "r"(a1), "r"(a2), "r"(a3), "r"(b0), "r"(b1));
}

__global__ void __launch_bounds__(256, 1)
gemm_tc_kernel(const float* __restrict__ bias, float* __restrict__ out) {
    extern __shared__ float sm[];
    float4* Wps = reinterpret_cast<float4*>(sm);        // 16*32*17 float4
    float*  Hs  = sm + 16 * 32 * WPAD * 4;              // BM * SW floats
    float*  Bs  = Hs + BM * SW;                         // F floats

    int tid  = threadIdx.x;
    int row0 = blockIdx.x * BM;

    // stage packed W: global [ks][lane][16] -> smem [ks][lane][17]
    for (int i = tid; i < 16 * 32 * 16; i += 256) {
        int nt = i & 15, rest = i >> 4;
        Wps[rest * WPAD + nt] = g_Wpk[i];
    }
    // stage H tile
    for (int i = tid; i < BM * (F / 4); i += 256) {
        int r = i / (F / 4), c4 = i % (F / 4);
        float4 v = make_float4(0.f, 0.f, 0.f, 0.f);
        int grow = row0 + r;
        if (grow < NN)
            v = reinterpret_cast<const float4*>(g_h)[grow * (F / 4) + c4];
        reinterpret_cast<float4*>(&Hs[r * SW + c4 * 4])[0] = v;
    }
    if (tid < F) Bs[tid] = bias[tid];
    __syncthreads();

    int warp = tid >> 5;
    int lane = tid & 31;
    int gid  = lane >> 2;
    int tg   = lane & 3;
    int rb   = warp * 16;

    float d[16][4];
#pragma unroll
    for (int nt = 0; nt < 16; nt++)
#pragma unroll
        for (int j = 0; j < 4; j++) d[nt][j] = 0.f;

#pragma unroll
    for (int ks = 0; ks < 16; ks++) {
        int k0 = ks * 8;
        float af0 = Hs[(rb + gid) * SW + k0 + tg];
        float af1 = Hs[(rb + gid + 8) * SW + k0 + tg];
        float af2 = Hs[(rb + gid) * SW + k0 + tg + 4];
        float af3 = Hs[(rb + gid + 8) * SW + k0 + tg + 4];
        float ah0 = to_tf32(af0), ah1 = to_tf32(af1);
        float ah2 = to_tf32(af2), ah3 = to_tf32(af3);
        uint32_t h0 = __float_as_uint(ah0), h1 = __float_as_uint(ah1);
        uint32_t h2 = __float_as_uint(ah2), h3 = __float_as_uint(ah3);
        uint32_t l0 = __float_as_uint(to_tf32(af0 - ah0));
        uint32_t l1 = __float_as_uint(to_tf32(af1 - ah1));
        uint32_t l2 = __float_as_uint(to_tf32(af2 - ah2));
        uint32_t l3 = __float_as_uint(to_tf32(af3 - ah3));

        const float4* wrow = &Wps[(ks * 32 + lane) * WPAD];
#pragma unroll
        for (int nt = 0; nt < 16; nt++) {
            float4 wb = wrow[nt];                          // one LDS.128
            uint32_t bh0 = __float_as_uint(wb.x);
            uint32_t bh1 = __float_as_uint(wb.y);
            uint32_t bl0 = __float_as_uint(wb.z);
            uint32_t bl1 = __float_as_uint(wb.w);
            mma_tf32(d[nt][0], d[nt][1], d[nt][2], d[nt][3], h0, h1, h2, h3, bh0, bh1);
            mma_tf32(d[nt][0], d[nt][1], d[nt][2], d[nt][3], h0, h1, h2, h3, bl0, bl1);
            mma_tf32(d[nt][0], d[nt][1], d[nt][2], d[nt][3], l0, l1, l2, l3, bh0, bh1);
        }
    }

    int rA = row0 + rb + gid;
    int rB = rA + 8;
#pragma unroll
    for (int nt = 0; nt < 16; nt++) {
        int col = nt * 8 + tg * 2;
        float b0 = Bs[col], b1 = Bs[col + 1];
        if (rA < NN) {
            float2 o = make_float2(d[nt][0] + b0, d[nt][1] + b1);
            reinterpret_cast<float2*>(out + (size_t)rA * F + col)[0] = o;
        }
        if (rB < NN) {
            float2 o = make_float2(d[nt][2] + b0, d[nt][3] + b1);
            reinterpret_cast<float2*>(out + (size_t)rB * F + col)[0] = o;
        }
    }
}

// ---------------------------------------------------------------------------
extern "C" void kernel_launch(void* const* d_in, const int* in_sizes, int n_in,
                              void* d_out, int out_size) {
    const float* x      = (const float*)d_in[0];
    const int*   src    = (const int*)d_in[1];
    const int*   dst    = (const int*)d_in[2];
    const float* weight = (const float*)d_in[3];
    const float* bias   = (const float*)d_in[4];
    float*       out    = (float*)d_out;

    init_kernel<<<(NN + 255) / 256, 256>>>(weight);
    deg_kernel<<<(NE + 255) / 256, 256>>>(src, dst);
    scan_kernel<<<NBLK, SCAN_B>>>();
    scatter_kernel<<<(NE / 4 + 255) / 256, 256>>>(src, dst);

    {
        long long threads = (long long)NN * 32;
        int blocks = (int)((threads + 255) / 256);
        agg_kernel<<<blocks, 256>>>(x);
    }
    {
        int smem = (16 * 32 * WPAD * 4 + BM * SW + F) * (int)sizeof(float); // 207360 B
        cudaFuncSetAttribute(gemm_tc_kernel, cudaFuncAttributeMaxDynamicSharedMemorySize, smem);
        gemm_tc_kernel<<<(NN + BM - 1) / BM, 256, smem>>>(bias, out);
    }
}

// round 8
// speedup vs baseline: 1.1805x; 1.1805x over previous
#include <cuda_runtime.h>
#include <cstdint>

#define NN 50000
#define NE 800000
#define F  128
#define SCAN_B 256
#define NBLK ((NN + SCAN_B - 1) / SCAN_B)   // 196

#define BM   128          // gemm rows per block
#define SW   132          // Hs padded row stride (floats)
#define WPAD 17           // Wpk padded nt stride (float4s)

// ---------------- device scratch (no allocations allowed) -------------------
__device__ int   g_deg_out_i[NN];
__device__ int   g_deg_in_i[NN];
__device__ int   g_row_start[NN];
__device__ float g_scale_out[NN];
__device__ int   g_slot[NE];            // edge's slot within its dst row
__device__ int   g_perm_src[NE];        // src indices grouped by dst
__device__ float g_h[NN * F];
__device__ float4 g_Wpk[16 * 32 * 16];  // fragment-ordered W (hi0,hi1,lo0,lo1)
__device__ int   g_scan_tmp[NN];
__device__ int   g_block_sums[NBLK];

__device__ __forceinline__ float to_tf32(float v) {
    uint32_t b;
    asm("cvt.rna.tf32.f32 %0, %1;" : "=r"(b) : "f"(v));
    return __uint_as_float(b);
}

// ---------------------------------------------------------------------------
// 1) init: zero degrees + build fragment-ordered W split
// ---------------------------------------------------------------------------
__global__ void init_kernel(const float* __restrict__ weight) {
    int i = blockIdx.x * blockDim.x + threadIdx.x;
    if (i < NN) { g_deg_out_i[i] = 0; g_deg_in_i[i] = 0; }
    if (i < 16 * 32 * 16) {
        int nt   = i & 15;
        int rest = i >> 4;
        int lane = rest & 31;
        int ks   = rest >> 5;
        int tg   = lane & 3;
        int gid  = lane >> 2;
        int k0 = ks * 8, n0 = nt * 8;
        float w0 = weight[(k0 + tg) * F + n0 + gid];
        float w1 = weight[(k0 + tg + 4) * F + n0 + gid];
        float h0 = to_tf32(w0), h1 = to_tf32(w1);
        g_Wpk[i] = make_float4(h0, h1, to_tf32(w0 - h0), to_tf32(w1 - h1));
    }
}

// ---------------------------------------------------------------------------
// 2) degree histograms; in-degree atomic return value = edge slot
// ---------------------------------------------------------------------------
__global__ void deg_kernel(const int* __restrict__ src, const int* __restrict__ dst) {
    int t = blockIdx.x * blockDim.x + threadIdx.x;
    int e0 = t * 2;
    if (e0 < NE) {
        int s0 = src[e0], s1 = src[e0 + 1];
        int d0 = dst[e0], d1 = dst[e0 + 1];
        atomicAdd(&g_deg_out_i[s0], 1);
        atomicAdd(&g_deg_out_i[s1], 1);
        g_slot[e0]     = atomicAdd(&g_deg_in_i[d0], 1);
        g_slot[e0 + 1] = atomicAdd(&g_deg_in_i[d1], 1);
    }
}

// ---------------------------------------------------------------------------
// 3) multi-block exclusive scan of deg_in (proven 3-kernel version)
// ---------------------------------------------------------------------------
__global__ void __launch_bounds__(SCAN_B)
scan1_kernel() {
    int idx  = blockIdx.x * SCAN_B + threadIdx.x;
    int lane = threadIdx.x & 31;
    int w    = threadIdx.x >> 5;
    int v    = (idx < NN) ? g_deg_in_i[idx] : 0;
    int x = v;
#pragma unroll
    for (int o = 1; o < 32; o <<= 1) {
        int t = __shfl_up_sync(0xffffffffu, x, o);
        if (lane >= o) x += t;
    }
    __shared__ int wsum[8];
    if (lane == 31) wsum[w] = x;
    __syncthreads();
    if (threadIdx.x < 8) {
        int s = wsum[threadIdx.x];
#pragma unroll
        for (int o = 1; o < 8; o <<= 1) {
            int t = __shfl_up_sync(0xffu, s, o);
            if ((int)threadIdx.x >= o) s += t;
        }
        wsum[threadIdx.x] = s;
    }
    __syncthreads();
    int woff = (w > 0) ? wsum[w - 1] : 0;
    if (idx < NN) g_scan_tmp[idx] = woff + x - v;
    if (threadIdx.x == SCAN_B - 1) g_block_sums[blockIdx.x] = wsum[7];
}

__global__ void __launch_bounds__(SCAN_B)
scan2_kernel() {
    int t    = threadIdx.x;
    int lane = t & 31;
    int w    = t >> 5;
    int v    = (t < NBLK) ? g_block_sums[t] : 0;
    int x = v;
#pragma unroll
    for (int o = 1; o < 32; o <<= 1) {
        int tt = __shfl_up_sync(0xffffffffu, x, o);
        if (lane >= o) x += tt;
    }
    __shared__ int wsum[8];
    if (lane == 31) wsum[w] = x;
    __syncthreads();
    if (t < 8) {
        int s = wsum[t];
#pragma unroll
        for (int o = 1; o < 8; o <<= 1) {
            int tt = __shfl_up_sync(0xffu, s, o);
            if (t >= o) s += tt;
        }
        wsum[t] = s;
    }
    __syncthreads();
    int woff = (w > 0) ? wsum[w - 1] : 0;
    if (t < NBLK) g_block_sums[t] = woff + x - v;
}

__global__ void __launch_bounds__(SCAN_B)
scan3_kernel() {
    int idx = blockIdx.x * SCAN_B + threadIdx.x;
    if (idx < NN) {
        g_row_start[idx] = g_scan_tmp[idx] + g_block_sums[blockIdx.x];
        g_scale_out[idx] = rsqrtf(fmaxf((float)g_deg_out_i[idx], 1.0f));
    }
}

// ---------------------------------------------------------------------------
// 4) atomic-free scatter: perm[row_start[dst] + slot] = src
// ---------------------------------------------------------------------------
__global__ void scatter_kernel(const int* __restrict__ src, const int* __restrict__ dst) {
    int t = blockIdx.x * blockDim.x + threadIdx.x;
    int e0 = t * 4;
    if (e0 < NE) {
        int4 d  = *reinterpret_cast<const int4*>(dst + e0);
        int4 s  = *reinterpret_cast<const int4*>(src + e0);
        int4 sl = *reinterpret_cast<const int4*>(g_slot + e0);
        g_perm_src[g_row_start[d.x] + sl.x] = s.x;
        g_perm_src[g_row_start[d.y] + sl.y] = s.y;
        g_perm_src[g_row_start[d.z] + sl.z] = s.z;
        g_perm_src[g_row_start[d.w] + sl.w] = s.w;
    }
}

// ---------------------------------------------------------------------------
// 5) CSR aggregation: one warp per node, both norms folded in.
// ---------------------------------------------------------------------------
__global__ void __launch_bounds__(256)
agg_kernel(const float* __restrict__ x) {
    int gtid = blockIdx.x * blockDim.x + threadIdx.x;
    int node = gtid >> 5;
    int lane = threadIdx.x & 31;
    if (node >= NN) return;

    int start = g_row_start[node];
    int len   = g_deg_in_i[node];
    const int* ps = g_perm_src + start;
    const float4* x4 = reinterpret_cast<const float4*>(x);

    float4 acc = make_float4(0.f, 0.f, 0.f, 0.f);
    int i = 0;
    for (; i + 4 <= len; i += 4) {
        int s0 = ps[i], s1 = ps[i + 1], s2 = ps[i + 2], s3 = ps[i + 3];
        float c0 = g_scale_out[s0], c1 = g_scale_out[s1];
        float c2 = g_scale_out[s2], c3 = g_scale_out[s3];
        float4 a0 = x4[(size_t)s0 * 32 + lane];
        float4 a1 = x4[(size_t)s1 * 32 + lane];
        float4 a2 = x4[(size_t)s2 * 32 + lane];
        float4 a3 = x4[(size_t)s3 * 32 + lane];
        acc.x += c0 * a0.x; acc.y += c0 * a0.y; acc.z += c0 * a0.z; acc.w += c0 * a0.w;
        acc.x += c1 * a1.x; acc.y += c1 * a1.y; acc.z += c1 * a1.z; acc.w += c1 * a1.w;
        acc.x += c2 * a2.x; acc.y += c2 * a2.y; acc.z += c2 * a2.z; acc.w += c2 * a2.w;
        acc.x += c3 * a3.x; acc.y += c3 * a3.y; acc.z += c3 * a3.z; acc.w += c3 * a3.w;
    }
    for (; i < len; i++) {
        int s0 = ps[i];
        float c0 = g_scale_out[s0];
        float4 a0 = x4[(size_t)s0 * 32 + lane];
        acc.x += c0 * a0.x; acc.y += c0 * a0.y; acc.z += c0 * a0.z; acc.w += c0 * a0.w;
    }
    float inv = rsqrtf(fmaxf((float)len, 1.0f));
    acc.x *= inv; acc.y *= inv; acc.z *= inv; acc.w *= inv;
    reinterpret_cast<float4*>(g_h + (size_t)node * F)[lane] = acc;
}

// ---------------------------------------------------------------------------
// 6) Tensor-core GEMM (3xTF32) with packed B fragments: out = h @ W + bias
// ---------------------------------------------------------------------------
__device__ __forceinline__ void mma_tf32(float& d0, float& d1, float& d2, float& d3,
                                         uint32_t a0, uint32_t a1, uint32_t a2, uint32_t a3,
                                         uint32_t b0, uint32_t b1) {
    asm volatile(
        "mma.sync.aligned.m16n8k8.row.col.f32.tf32.tf32.f32 "
        "{%0,%1,%2,%3}, {%4,%5,%6,%7}, {%8,%9}, {%0,%1,%2,%3};"
        : "+f"(d0), "+f"(d1), "+f"(d2), "+f"(d3)
        : "r"(a0), "r"(a1), "r"(a2), "r"(a3), "r"(b0), "r"(b1));
}

__global__ void __launch_bounds__(256, 1)
gemm_tc_kernel(const float* __restrict__ bias, float* __restrict__ out) {
    extern __shared__ float sm[];
    float4* Wps = reinterpret_cast<float4*>(sm);        // 16*32*17 float4
    float*  Hs  = sm + 16 * 32 * WPAD * 4;              // BM * SW floats
    float*  Bs  = Hs + BM * SW;                         // F floats

    int tid  = threadIdx.x;
    int row0 = blockIdx.x * BM;

    for (int i = tid; i < 16 * 32 * 16; i += 256) {
        int nt = i & 15, rest = i >> 4;
        Wps[rest * WPAD + nt] = g_Wpk[i];
    }
    for (int i = tid; i < BM * (F / 4); i += 256) {
        int r = i / (F / 4), c4 = i % (F / 4);
        float4 v = make_float4(0.f, 0.f, 0.f, 0.f);
        int grow = row0 + r;
        if (grow < NN)
            v = reinterpret_cast<const float4*>(g_h)[grow * (F / 4) + c4];
        reinterpret_cast<float4*>(&Hs[r * SW + c4 * 4])[0] = v;
    }
    if (tid < F) Bs[tid] = bias[tid];
    __syncthreads();

    int warp = tid >> 5;
    int lane = tid & 31;
    int gid  = lane >> 2;
    int tg   = lane & 3;
    int rb   = warp * 16;

    float d[16][4];
#pragma unroll
    for (int nt = 0; nt < 16; nt++)
#pragma unroll
        for (int j = 0; j < 4; j++) d[nt][j] = 0.f;

#pragma unroll
    for (int ks = 0; ks < 16; ks++) {
        int k0 = ks * 8;
        float af0 = Hs[(rb + gid) * SW + k0 + tg];
        float af1 = Hs[(rb + gid + 8) * SW + k0 + tg];
        float af2 = Hs[(rb + gid) * SW + k0 + tg + 4];
        float af3 = Hs[(rb + gid + 8) * SW + k0 + tg + 4];
        float ah0 = to_tf32(af0), ah1 = to_tf32(af1);
        float ah2 = to_tf32(af2), ah3 = to_tf32(af3);
        uint32_t h0 = __float_as_uint(ah0), h1 = __float_as_uint(ah1);
        uint32_t h2 = __float_as_uint(ah2), h3 = __float_as_uint(ah3);
        uint32_t l0 = __float_as_uint(to_tf32(af0 - ah0));
        uint32_t l1 = __float_as_uint(to_tf32(af1 - ah1));
        uint32_t l2 = __float_as_uint(to_tf32(af2 - ah2));
        uint32_t l3 = __float_as_uint(to_tf32(af3 - ah3));

        const float4* wrow = &Wps[(ks * 32 + lane) * WPAD];
#pragma unroll
        for (int nt = 0; nt < 16; nt++) {
            float4 wb = wrow[nt];                          // one LDS.128
            uint32_t bh0 = __float_as_uint(wb.x);
            uint32_t bh1 = __float_as_uint(wb.y);
            uint32_t bl0 = __float_as_uint(wb.z);
            uint32_t bl1 = __float_as_uint(wb.w);
            mma_tf32(d[nt][0], d[nt][1], d[nt][2], d[nt][3], h0, h1, h2, h3, bh0, bh1);
            mma_tf32(d[nt][0], d[nt][1], d[nt][2], d[nt][3], h0, h1, h2, h3, bl0, bl1);
            mma_tf32(d[nt][0], d[nt][1], d[nt][2], d[nt][3], l0, l1, l2, l3, bh0, bh1);
        }
    }

    int rA = row0 + rb + gid;
    int rB = rA + 8;
#pragma unroll
    for (int nt = 0; nt < 16; nt++) {
        int col = nt * 8 + tg * 2;
        float b0 = Bs[col], b1 = Bs[col + 1];
        if (rA < NN) {
            float2 o = make_float2(d[nt][0] + b0, d[nt][1] + b1);
            reinterpret_cast<float2*>(out + (size_t)rA * F + col)[0] = o;
        }
        if (rB < NN) {
            float2 o = make_float2(d[nt][2] + b0, d[nt][3] + b1);
            reinterpret_cast<float2*>(out + (size_t)rB * F + col)[0] = o;
        }
    }
}

// ---------------------------------------------------------------------------
extern "C" void kernel_launch(void* const* d_in, const int* in_sizes, int n_in,
                              void* d_out, int out_size) {
    const float* x      = (const float*)d_in[0];
    const int*   src    = (const int*)d_in[1];
    const int*   dst    = (const int*)d_in[2];
    const float* weight = (const float*)d_in[3];
    const float* bias   = (const float*)d_in[4];
    float*       out    = (float*)d_out;

    init_kernel<<<(NN + 255) / 256, 256>>>(weight);
    deg_kernel<<<(NE / 2 + 255) / 256, 256>>>(src, dst);
    scan1_kernel<<<NBLK, SCAN_B>>>();
    scan2_kernel<<<1, SCAN_B>>>();
    scan3_kernel<<<NBLK, SCAN_B>>>();
    scatter_kernel<<<(NE / 4 + 255) / 256, 256>>>(src, dst);

    {
        long long threads = (long long)NN * 32;
        int blocks = (int)((threads + 255) / 256);
        agg_kernel<<<blocks, 256>>>(x);
    }
    {
        int smem = (16 * 32 * WPAD * 4 + BM * SW + F) * (int)sizeof(float); // 207360 B
        cudaFuncSetAttribute(gemm_tc_kernel, cudaFuncAttributeMaxDynamicSharedMemorySize, smem);
        gemm_tc_kernel<<<(NN + BM - 1) / BM, 256, smem>>>(bias, out);
    }
}

// round 9
// speedup vs baseline: 1.3307x; 1.1273x over previous
#include <cuda_runtime.h>
#include <cuda_fp16.h>
#include <cstdint>

#define NN 50000
#define NE 800000
#define F  128
#define SCAN_B 256
#define NBLK ((NN + SCAN_B - 1) / SCAN_B)   // 196

#define BM   64           // gemm rows per block
#define GT   128          // gemm threads (4 warps x 16 rows)
#define SW   132          // Hs padded row stride (floats)
#define WPAD 17           // Wpk padded nt stride (uint4s)
#define KSP  8            // k-steps of 16

// ---------------- device scratch (no allocations allowed) -------------------
__device__ int   g_deg_out_i[NN];
__device__ int   g_deg_in_i[NN];
__device__ int   g_row_start[NN];
__device__ float g_scale_out[NN];
__device__ int   g_slot[NE];
__device__ int   g_perm_src[NE];
__device__ float g_h[NN * F];
__device__ uint4 g_Wpk[KSP * 32 * 16];     // fp16 frags {bh0,bh1,bl0,bl1}
__device__ int   g_scan_tmp[NN];
__device__ int   g_block_sums[NBLK];

__device__ __forceinline__ uint32_t h2u(half2 h) {
    return *reinterpret_cast<uint32_t*>(&h);
}

// ---------------------------------------------------------------------------
// 1) init: zero degrees + fp16-split fragment-ordered W
//    layout: idx = (ks*32 + lane)*16 + nt ;  t=lane&3, g=lane>>2
//    b0 = {W[k0+2t][n0+g], W[k0+2t+1][n0+g]},  b1 = rows +8,+9
// ---------------------------------------------------------------------------
__global__ void init_kernel(const float* __restrict__ weight) {
    int i = blockIdx.x * blockDim.x + threadIdx.x;
    if (i < NN) { g_deg_out_i[i] = 0; g_deg_in_i[i] = 0; }
    if (i < KSP * 32 * 16) {
        int nt   = i & 15;
        int rest = i >> 4;
        int lane = rest & 31;
        int ks   = rest >> 5;
        int t    = lane & 3;
        int g    = lane >> 2;
        int k0 = ks * 16, n0 = nt * 8;
        float w00 = weight[(k0 + 2 * t)     * F + n0 + g];
        float w01 = weight[(k0 + 2 * t + 1) * F + n0 + g];
        float w10 = weight[(k0 + 2 * t + 8) * F + n0 + g];
        float w11 = weight[(k0 + 2 * t + 9) * F + n0 + g];
        half2 h0 = __floats2half2_rn(w00, w01);
        half2 h1 = __floats2half2_rn(w10, w11);
        half2 l0 = __floats2half2_rn(w00 - __half2float(__low2half(h0)),
                                     w01 - __half2float(__high2half(h0)));
        half2 l1 = __floats2half2_rn(w10 - __half2float(__low2half(h1)),
                                     w11 - __half2float(__high2half(h1)));
        g_Wpk[i] = make_uint4(h2u(h0), h2u(h1), h2u(l0), h2u(l1));
    }
}

// ---------------------------------------------------------------------------
// 2) degrees; in-degree atomic return value = edge slot
// ---------------------------------------------------------------------------
__global__ void deg_kernel(const int* __restrict__ src, const int* __restrict__ dst) {
    int t = blockIdx.x * blockDim.x + threadIdx.x;
    int e0 = t * 2;
    if (e0 < NE) {
        int s0 = src[e0], s1 = src[e0 + 1];
        int d0 = dst[e0], d1 = dst[e0 + 1];
        atomicAdd(&g_deg_out_i[s0], 1);
        atomicAdd(&g_deg_out_i[s1], 1);
        g_slot[e0]     = atomicAdd(&g_deg_in_i[d0], 1);
        g_slot[e0 + 1] = atomicAdd(&g_deg_in_i[d1], 1);
    }
}

// ---------------------------------------------------------------------------
// 3a) per-block exclusive scan of deg_in -> scan_tmp + block sums
// ---------------------------------------------------------------------------
__global__ void __launch_bounds__(SCAN_B)
scan1_kernel() {
    int idx  = blockIdx.x * SCAN_B + threadIdx.x;
    int lane = threadIdx.x & 31;
    int w    = threadIdx.x >> 5;
    int v    = (idx < NN) ? g_deg_in_i[idx] : 0;
    int x = v;
#pragma unroll
    for (int o = 1; o < 32; o <<= 1) {
        int t = __shfl_up_sync(0xffffffffu, x, o);
        if (lane >= o) x += t;
    }
    __shared__ int wsum[8];
    if (lane == 31) wsum[w] = x;
    __syncthreads();
    if (threadIdx.x < 8) {
        int s = wsum[threadIdx.x];
#pragma unroll
        for (int o = 1; o < 8; o <<= 1) {
            int t = __shfl_up_sync(0xffu, s, o);
            if ((int)threadIdx.x >= o) s += t;
        }
        wsum[threadIdx.x] = s;
    }
    __syncthreads();
    int woff = (w > 0) ? wsum[w - 1] : 0;
    if (idx < NN) g_scan_tmp[idx] = woff + x - v;
    if (threadIdx.x == SCAN_B - 1) g_block_sums[blockIdx.x] = wsum[7];
}

// ---------------------------------------------------------------------------
// 3b) apply: each block reduces its preceding block sums itself (no scan2)
// ---------------------------------------------------------------------------
__global__ void __launch_bounds__(SCAN_B)
scan3_kernel() {
    int bid  = blockIdx.x;
    int t    = threadIdx.x;
    int lane = t & 31;
    int w    = t >> 5;
    int v = (t < bid && t < NBLK) ? g_block_sums[t] : 0;   // NBLK <= 256
#pragma unroll
    for (int o = 16; o > 0; o >>= 1) v += __shfl_down_sync(0xffffffffu, v, o);
    __shared__ int wsum[8];
    __shared__ int s_base;
    if (lane == 0) wsum[w] = v;
    __syncthreads();
    if (t == 0) {
        int s = 0;
#pragma unroll
        for (int j = 0; j < 8; j++) s += wsum[j];
        s_base = s;
    }
    __syncthreads();
    int idx = bid * SCAN_B + t;
    if (idx < NN) {
        g_row_start[idx] = g_scan_tmp[idx] + s_base;
        g_scale_out[idx] = rsqrtf(fmaxf((float)g_deg_out_i[idx], 1.0f));
    }
}

// ---------------------------------------------------------------------------
// 4) atomic-free scatter: perm[row_start[dst] + slot] = src
// ---------------------------------------------------------------------------
__global__ void scatter_kernel(const int* __restrict__ src, const int* __restrict__ dst) {
    int t = blockIdx.x * blockDim.x + threadIdx.x;
    int e0 = t * 4;
    if (e0 < NE) {
        int4 d  = *reinterpret_cast<const int4*>(dst + e0);
        int4 s  = *reinterpret_cast<const int4*>(src + e0);
        int4 sl = *reinterpret_cast<const int4*>(g_slot + e0);
        g_perm_src[g_row_start[d.x] + sl.x] = s.x;
        g_perm_src[g_row_start[d.y] + sl.y] = s.y;
        g_perm_src[g_row_start[d.z] + sl.z] = s.z;
        g_perm_src[g_row_start[d.w] + sl.w] = s.w;
    }
}

// ---------------------------------------------------------------------------
// 5) CSR aggregation: one warp per node, both norms folded in.
// ---------------------------------------------------------------------------
__global__ void __launch_bounds__(256)
agg_kernel(const float* __restrict__ x) {
    int gtid = blockIdx.x * blockDim.x + threadIdx.x;
    int node = gtid >> 5;
    int lane = threadIdx.x & 31;
    if (node >= NN) return;

    int start = g_row_start[node];
    int len   = g_deg_in_i[node];
    const int* ps = g_perm_src + start;
    const float4* x4 = reinterpret_cast<const float4*>(x);

    float4 acc = make_float4(0.f, 0.f, 0.f, 0.f);
    int i = 0;
    for (; i + 4 <= len; i += 4) {
        int s0 = ps[i], s1 = ps[i + 1], s2 = ps[i + 2], s3 = ps[i + 3];
        float c0 = g_scale_out[s0], c1 = g_scale_out[s1];
        float c2 = g_scale_out[s2], c3 = g_scale_out[s3];
        float4 a0 = x4[(size_t)s0 * 32 + lane];
        float4 a1 = x4[(size_t)s1 * 32 + lane];
        float4 a2 = x4[(size_t)s2 * 32 + lane];
        float4 a3 = x4[(size_t)s3 * 32 + lane];
        acc.x += c0 * a0.x; acc.y += c0 * a0.y; acc.z += c0 * a0.z; acc.w += c0 * a0.w;
        acc.x += c1 * a1.x; acc.y += c1 * a1.y; acc.z += c1 * a1.z; acc.w += c1 * a1.w;
        acc.x += c2 * a2.x; acc.y += c2 * a2.y; acc.z += c2 * a2.z; acc.w += c2 * a2.w;
        acc.x += c3 * a3.x; acc.y += c3 * a3.y; acc.z += c3 * a3.z; acc.w += c3 * a3.w;
    }
    for (; i < len; i++) {
        int s0 = ps[i];
        float c0 = g_scale_out[s0];
        float4 a0 = x4[(size_t)s0 * 32 + lane];
        acc.x += c0 * a0.x; acc.y += c0 * a0.y; acc.z += c0 * a0.z; acc.w += c0 * a0.w;
    }
    float inv = rsqrtf(fmaxf((float)len, 1.0f));
    acc.x *= inv; acc.y *= inv; acc.z *= inv; acc.w *= inv;
    reinterpret_cast<float4*>(g_h + (size_t)node * F)[lane] = acc;
}

// ---------------------------------------------------------------------------
// 6) GEMM via 2-way fp16-split HMMA m16n8k16: out = h @ W + bias
//    Block: 128 thr / 4 warps, 64 rows; warp tile 16 rows x 128 cols.
//    3 mmas per (ks,nt): Ah*Bh + Ah*Bl + Al*Bh.  occ 2.
// ---------------------------------------------------------------------------
__device__ __forceinline__ void mma_f16(float& d0, float& d1, float& d2, float& d3,
                                        uint32_t a0, uint32_t a1, uint32_t a2, uint32_t a3,
                                        uint32_t b0, uint32_t b1) {
    asm volatile(
        "mma.sync.aligned.m16n8k16.row.col.f32.f16.f16.f32 "
        "{%0,%1,%2,%3}, {%4,%5,%6,%7}, {%8,%9}, {%0,%1,%2,%3};"
        : "+f"(d0), "+f"(d1), "+f"(d2), "+f"(d3)
        : "r"(a0), "r"(a1), "r"(a2), "r"(a3), "r"(b0), "r"(b1));
}

__device__ __forceinline__ void split2(float2 f, uint32_t& hi, uint32_t& lo) {
    half2 h = __floats2half2_rn(f.x, f.y);
    half2 l = __floats2half2_rn(f.x - __half2float(__low2half(h)),
                                f.y - __half2float(__high2half(h)));
    hi = h2u(h); lo = h2u(l);
}

__global__ void __launch_bounds__(GT, 2)
gemm_tc_kernel(const float* __restrict__ bias, float* __restrict__ out) {
    extern __shared__ float sm[];
    uint4* Wps = reinterpret_cast<uint4*>(sm);          // KSP*32*17 uint4
    float* Hs  = sm + KSP * 32 * WPAD * 4;              // BM * SW floats
    float* Bs  = Hs + BM * SW;                          // F floats

    int tid  = threadIdx.x;
    int row0 = blockIdx.x * BM;

    for (int i = tid; i < KSP * 32 * 16; i += GT) {
        int nt = i & 15, rest = i >> 4;
        Wps[rest * WPAD + nt] = g_Wpk[i];
    }
    for (int i = tid; i < BM * (F / 4); i += GT) {
        int r = i / (F / 4), c4 = i % (F / 4);
        float4 v = make_float4(0.f, 0.f, 0.f, 0.f);
        int grow = row0 + r;
        if (grow < NN)
            v = reinterpret_cast<const float4*>(g_h)[grow * (F / 4) + c4];
        reinterpret_cast<float4*>(&Hs[r * SW + c4 * 4])[0] = v;
    }
    if (tid < F) Bs[tid] = bias[tid];
    __syncthreads();

    int warp = tid >> 5;
    int lane = tid & 31;
    int g    = lane >> 2;     // groupID 0..7
    int t    = lane & 3;      // thread-in-group
    int rb   = warp * 16;

    float d[16][4];
#pragma unroll
    for (int nt = 0; nt < 16; nt++)
#pragma unroll
        for (int j = 0; j < 4; j++) d[nt][j] = 0.f;

#pragma unroll
    for (int ks = 0; ks < KSP; ks++) {
        int k0 = ks * 16;
        float2 f00 = *reinterpret_cast<float2*>(&Hs[(rb + g)     * SW + k0 + 2 * t]);
        float2 f10 = *reinterpret_cast<float2*>(&Hs[(rb + g + 8) * SW + k0 + 2 * t]);
        float2 f01 = *reinterpret_cast<float2*>(&Hs[(rb + g)     * SW + k0 + 2 * t + 8]);
        float2 f11 = *reinterpret_cast<float2*>(&Hs[(rb + g + 8) * SW + k0 + 2 * t + 8]);
        uint32_t ah0, al0, ah1, al1, ah2, al2, ah3, al3;
        split2(f00, ah0, al0);
        split2(f10, ah1, al1);
        split2(f01, ah2, al2);
        split2(f11, ah3, al3);

        const uint4* wrow = &Wps[(ks * 32 + lane) * WPAD];
#pragma unroll
        for (int nt = 0; nt < 16; nt++) {
            uint4 wb = wrow[nt];                           // one LDS.128
            mma_f16(d[nt][0], d[nt][1], d[nt][2], d[nt][3],
                    ah0, ah1, ah2, ah3, wb.x, wb.y);       // Ah*Bh
            mma_f16(d[nt][0], d[nt][1], d[nt][2], d[nt][3],
                    ah0, ah1, ah2, ah3, wb.z, wb.w);       // Ah*Bl
            mma_f16(d[nt][0], d[nt][1], d[nt][2], d[nt][3],
                    al0, al1, al2, al3, wb.x, wb.y);       // Al*Bh
        }
    }

    int rA = row0 + rb + g;
    int rB = rA + 8;
#pragma unroll
    for (int nt = 0; nt < 16; nt++) {
        int col = nt * 8 + t * 2;
        float b0 = Bs[col], b1 = Bs[col + 1];
        if (rA < NN) {
            float2 o = make_float2(d[nt][0] + b0, d[nt][1] + b1);
            reinterpret_cast<float2*>(out + (size_t)rA * F + col)[0] = o;
        }
        if (rB < NN) {
            float2 o = make_float2(d[nt][2] + b0, d[nt][3] + b1);
            reinterpret_cast<float2*>(out + (size_t)rB * F + col)[0] = o;
        }
    }
}

// ---------------------------------------------------------------------------
extern "C" void kernel_launch(void* const* d_in, const int* in_sizes, int n_in,
                              void* d_out, int out_size) {
    const float* x      = (const float*)d_in[0];
    const int*   src    = (const int*)d_in[1];
    const int*   dst    = (const int*)d_in[2];
    const float* weight = (const float*)d_in[3];
    const float* bias   = (const float*)d_in[4];
    float*       out    = (float*)d_out;

    init_kernel<<<(NN + 255) / 256, 256>>>(weight);
    deg_kernel<<<(NE / 2 + 255) / 256, 256>>>(src, dst);
    scan1_kernel<<<NBLK, SCAN_B>>>();
    scan3_kernel<<<NBLK, SCAN_B>>>();
    scatter_kernel<<<(NE / 4 + 255) / 256, 256>>>(src, dst);

    {
        long long threads = (long long)NN * 32;
        int blocks = (int)((threads + 255) / 256);
        agg_kernel<<<blocks, 256>>>(x);
    }
    {
        int smem = (KSP * 32 * WPAD * 4 + BM * SW + F) * (int)sizeof(float); // 103936 B
        cudaFuncSetAttribute(gemm_tc_kernel, cudaFuncAttributeMaxDynamicSharedMemorySize, smem);
        gemm_tc_kernel<<<(NN + BM - 1) / BM, GT, smem>>>(bias, out);
    }
}